// round 14
// baseline (speedup 1.0000x reference)
#include <cuda_runtime.h>
#include <cuda_fp16.h>
#include <stdint.h>
#include <math.h>

// ---------------- problem constants ----------------
#define MDIM 131072   // B*N rows
#define KDIM 512      // D
#define NDIM 512      // H
#define NNODES 2048
#define HALFN 1024

#define TILE_M 128
#define TILE_N 128
#define KC 32
#define NCHUNK 16
#define THREADS 512
#define NSLAB 1024
#define PITCH 80      // bytes per row in fp16 limb tiles (64 data + 16 pad)

// smem (bytes from 128-aligned dyn base), 3 stages:
//   A limbs: (s*2+p)*10240     -> 0..61440
//   B limbs: 61440 + (s*2+p)*10240 -> ..122880
//   stat red: 122880 (2 x 2KB)
#define A_OFF(s, p) ((((s) * 2) + (p)) * 10240)
#define B_OFF(s, p) (61440 + (((s) * 2) + (p)) * 10240)
#define SRED_S      122880
#define SRED_Q      124928
#define SMEM_BYTES  (126976 + 128)
#define HPITCH 132            // floats; epilogue staging (reuses tile region)
#define SCALE_UP 4096.0f
#define SCALE_DN (1.0f / 4096.0f)

// ---------------- device scratch ----------------
__device__ float  g_h[(size_t)MDIM * NDIM];        // 256 MB hidden
__device__ float  g_ps[NDIM * NSLAB];              // column-major partials [col][slab]
__device__ float  g_pq[NDIM * NSLAB];
__device__ float  g_a[NDIM];
__device__ float  g_c[NDIM];
__device__ __align__(16) __half g_Bh[KDIM * NDIM]; // W1^T limbs, [n][k]
__device__ __align__(16) __half g_Bm[KDIM * NDIM]; // scaled by 4096

// ---------------- PTX helpers ----------------
__device__ __forceinline__ uint32_t smem_u32(const void* p) {
    uint32_t a;
    asm("{ .reg .u64 t; cvta.to.shared.u64 t, %1; cvt.u32.u64 %0, t; }" : "=r"(a) : "l"(p));
    return a;
}
#define LDS128(r0, r1, r2, r3, addr) \
    asm volatile("ld.shared.v4.b32 {%0, %1, %2, %3}, [%4];" \
                 : "=r"(r0), "=r"(r1), "=r"(r2), "=r"(r3) : "r"(addr))
#define LDS32(r0, addr) \
    asm volatile("ld.shared.b32 %0, [%1];" : "=r"(r0) : "r"(addr))
#define STS128(r0, r1, r2, r3, addr) \
    asm volatile("st.shared.v4.b32 [%0], {%1, %2, %3, %4};" \
                 :: "r"(addr), "r"(r0), "r"(r1), "r"(r2), "r"(r3) : "memory")
#define STS64F(addr, x, y) \
    asm volatile("st.shared.v2.f32 [%0], {%1, %2};" :: "r"(addr), "f"(x), "f"(y) : "memory")
#define STS32F(addr, x) \
    asm volatile("st.shared.f32 [%0], %1;" :: "r"(addr), "f"(x) : "memory")

__device__ __forceinline__ void ldsm_x4(uint32_t* r, uint32_t addr) {
    asm volatile("ldmatrix.sync.aligned.m8n8.x4.shared.b16 {%0,%1,%2,%3}, [%4];"
                 : "=r"(r[0]), "=r"(r[1]), "=r"(r[2]), "=r"(r[3]) : "r"(addr));
}
__device__ __forceinline__ void mma16816(float* d, const uint32_t* a, const uint32_t* b) {
    asm volatile(
        "mma.sync.aligned.m16n8k16.row.col.f32.f16.f16.f32 "
        "{%0,%1,%2,%3}, {%4,%5,%6,%7}, {%8,%9}, {%0,%1,%2,%3};"
        : "+f"(d[0]), "+f"(d[1]), "+f"(d[2]), "+f"(d[3])
        : "r"(a[0]), "r"(a[1]), "r"(a[2]), "r"(a[3]), "r"(b[0]), "r"(b[1]));
}
__device__ __forceinline__ void cpasync16(uint32_t dst, const void* src) {
    asm volatile("cp.async.cg.shared.global [%0], [%1], 16;" :: "r"(dst), "l"(src));
}
#define CP_COMMIT() asm volatile("cp.async.commit_group;" ::: "memory")
#define CP_WAIT1()  asm volatile("cp.async.wait_group 1;" ::: "memory")
#define CP_WAIT0()  asm volatile("cp.async.wait_group 0;" ::: "memory")

// scalar split (splitB only)
__device__ __forceinline__ void split2(float v, uint32_t& h, uint32_t& m) {
    __half hh = __float2half_rn(v);
    float r = (v - __half2float(hh)) * SCALE_UP;
    __half hm = __float2half_rn(r);
    h = (uint32_t)__half_as_ushort(hh);
    m = (uint32_t)__half_as_ushort(hm);
}

// packed split of a float pair
__device__ __forceinline__ void split2x2(float x0, float x1, uint32_t& hp, uint32_t& mp) {
    __half2 hh = __floats2half2_rn(x0, x1);
    float2 hf = __half22float2(hh);
    __half2 mm = __floats2half2_rn((x0 - hf.x) * SCALE_UP, (x1 - hf.y) * SCALE_UP);
    hp = *(uint32_t*)&hh;
    mp = *(uint32_t*)&mm;
}

// ---------------------------------------------------------------------------
// K1: split W1 [k][n] fp32 -> 2 fp16 matrices [n][k]; smem-tiled transpose
// ---------------------------------------------------------------------------
__global__ void __launch_bounds__(256) splitB_kernel(const float* __restrict__ W1) {
    __shared__ unsigned short sh[64][80];
    __shared__ unsigned short sm[64][80];
    const int n0 = (blockIdx.x & 7) * 64;
    const int k0 = (blockIdx.x >> 3) * 64;
    const int tid = threadIdx.x;

#pragma unroll
    for (int t = 0; t < 16; t++) {
        int idx = t * 256 + tid;
        int kk = idx >> 6, nn = idx & 63;
        float v = W1[(size_t)(k0 + kk) * NDIM + n0 + nn];
        uint32_t h, m;
        split2(v, h, m);
        sh[nn][kk] = (unsigned short)h;
        sm[nn][kk] = (unsigned short)m;
    }
    __syncthreads();

#pragma unroll
    for (int t = 0; t < 2; t++) {
        int idx = t * 256 + tid;
        int nn = idx >> 3, seg = idx & 7;
        uint4 vh = *(const uint4*)&sh[nn][seg * 8];
        uint4 vm = *(const uint4*)&sm[nn][seg * 8];
        *(uint4*)&g_Bh[(size_t)(n0 + nn) * KDIM + k0 + seg * 8] = vh;
        *(uint4*)&g_Bm[(size_t)(n0 + nn) * KDIM + k0 + seg * 8] = vm;
    }
}

// ---------------------------------------------------------------------------
// K2: fp16x2 HMMA GEMM  h = x @ W1 + b1, fused per-CTA column stats
// 512 threads, warp tile 32x32, 3-stage pipeline, convert mid-MMA  (champion)
// ---------------------------------------------------------------------------
__device__ __forceinline__ void issue_B(uint32_t base, int n0, int c, int tid) {
    const int s = c % 3;
    int p = tid >> 8;
    int r = (tid >> 1) & 127;
    int sg = (tid & 1) * 32;
    const __half* gb = (p == 0) ? g_Bh : g_Bm;
    const __half* src = gb + (size_t)(n0 + r) * KDIM + c * KC + (sg >> 1);
    uint32_t dst = base + B_OFF(s, p) + r * PITCH + sg;
    cpasync16(dst, src);
    cpasync16(dst + 16, src + 8);
    CP_COMMIT();
}

__device__ __forceinline__ void ldg_x(const float* __restrict__ X, int m0, int c,
                                      int xrow, int xf, float4& xa, float4& xb) {
    const float4* src = (const float4*)(X + (size_t)(m0 + xrow) * KDIM + c * KC + xf);
    xa = src[0];
    xb = src[1];
}

__device__ __forceinline__ void convert_sts(uint32_t base, int c, int xrow, int xf,
                                            const float4& xa, const float4& xb) {
    const int s = c % 3;
    uint32_t h0, h1, h2, h3, m0v, m1, m2, m3;
    split2x2(xa.x, xa.y, h0, m0v);
    split2x2(xa.z, xa.w, h1, m1);
    split2x2(xb.x, xb.y, h2, m2);
    split2x2(xb.z, xb.w, h3, m3);
    uint32_t ro = (uint32_t)(xrow * PITCH + xf * 2);
    STS128(h0, h1, h2, h3, base + A_OFF(s, 0) + ro);
    STS128(m0v, m1, m2, m3, base + A_OFF(s, 1) + ro);
}

__global__ void __launch_bounds__(THREADS, 1)
gemm_kernel(const float* __restrict__ X, const float* __restrict__ b1) {
    extern __shared__ char dyn[];
    __shared__ float sbias[TILE_N];

    const uint32_t base = (smem_u32(dyn) + 127u) & ~127u;
    const int tid = threadIdx.x;
    const int wid = tid >> 5;
    const int lane = tid & 31;
    const int m0 = blockIdx.y * TILE_M;
    const int n0 = blockIdx.x * TILE_N;

    if (tid < TILE_N) sbias[tid] = b1[n0 + tid];

    const int wm = (wid & 3) * 32;
    const int wn = (wid >> 2) * 32;
    const int xrow = tid >> 2;
    const int xf = (tid & 3) * 8;

    float a1[2][4][4], a2[2][4][4];
#pragma unroll
    for (int i = 0; i < 2; i++)
#pragma unroll
        for (int j = 0; j < 4; j++)
#pragma unroll
            for (int q = 0; q < 4; q++) { a1[i][j][q] = 0.f; a2[i][j][q] = 0.f; }

    // prologue: chunks 0 and 1
    {
        float4 xa, xb;
        issue_B(base, n0, 0, tid);
        issue_B(base, n0, 1, tid);
        ldg_x(X, m0, 0, xrow, xf, xa, xb);
        convert_sts(base, 0, xrow, xf, xa, xb);
        ldg_x(X, m0, 1, xrow, xf, xa, xb);
        convert_sts(base, 1, xrow, xf, xa, xb);
        CP_WAIT1();   // B(0) complete
        __syncthreads();
    }

    // lane-constant ldsm address components
    const int arow = lane & 15;
    const int acolh = (lane >> 4) * 16;
    const int bm = lane >> 3;
    const int brow = ((bm & 2) << 2) + (lane & 7);
    const int bko = (bm & 1) * 16;

    for (int c = 0; c < NCHUNK; c++) {
        const int s = c % 3;
        float4 xa, xb;
        const bool pre = (c + 2 < NCHUNK);
        if (pre) {
            ldg_x(X, m0, c + 2, xrow, xf, xa, xb);   // consumed mid-MMA below
            issue_B(base, n0, c + 2, tid);
        }

#pragma unroll
        for (int k16 = 0; k16 < 2; k16++) {
            const uint32_t koA = (uint32_t)(k16 * 32 + acolh);
            const uint32_t koB = (uint32_t)(k16 * 32 + bko);
            uint32_t aH[2][4], aM[2][4];
#pragma unroll
            for (int i = 0; i < 2; i++) {
                uint32_t ra = (uint32_t)((wm + i * 16 + arow) * PITCH);
                ldsm_x4(aH[i], base + A_OFF(s, 0) + ra + koA);
                ldsm_x4(aM[i], base + A_OFF(s, 1) + ra + koA);
            }
#pragma unroll
            for (int jj = 0; jj < 2; jj++) {
                uint32_t rb = (uint32_t)((wn + jj * 16 + brow) * PITCH) + koB;
                uint32_t bh[4], bmr[4];
                ldsm_x4(bh, base + B_OFF(s, 0) + rb);
                ldsm_x4(bmr, base + B_OFF(s, 1) + rb);
#pragma unroll
                for (int i = 0; i < 2; i++) {
                    mma16816(a1[i][jj * 2 + 0], aH[i], bh + 0);
                    mma16816(a1[i][jj * 2 + 1], aH[i], bh + 2);
                    mma16816(a2[i][jj * 2 + 0], aM[i], bh + 0);
                    mma16816(a2[i][jj * 2 + 1], aM[i], bh + 2);
                    mma16816(a2[i][jj * 2 + 0], aH[i], bmr + 0);
                    mma16816(a2[i][jj * 2 + 1], aH[i], bmr + 2);
                }
            }
            // convert sandwiched between the two k16 MMA batches
            if (k16 == 0 && pre) convert_sts(base, c + 2, xrow, xf, xa, xb);
        }

        if (pre) {
            CP_WAIT1();          // B(c+1) complete
        } else if (c + 1 < NCHUNK) {
            CP_WAIT0();
        }
        if (c + 1 < NCHUNK) __syncthreads();
    }

    // ---------------- epilogue: combine limbs, stage to smem ----------------
    __syncthreads();
#pragma unroll
    for (int i = 0; i < 2; i++)
#pragma unroll
        for (int j = 0; j < 4; j++) {
            int r0 = wm + i * 16 + (lane >> 2);
            int c0 = wn + j * 8 + (lane & 3) * 2;
            float v0 = a1[i][j][0] + a2[i][j][0] * SCALE_DN;
            float v1 = a1[i][j][1] + a2[i][j][1] * SCALE_DN;
            float v2 = a1[i][j][2] + a2[i][j][2] * SCALE_DN;
            float v3 = a1[i][j][3] + a2[i][j][3] * SCALE_DN;
            STS64F(base + (uint32_t)((r0 * HPITCH + c0) * 4), v0, v1);
            STS64F(base + (uint32_t)(((r0 + 8) * HPITCH + c0) * 4), v2, v3);
        }
    __syncthreads();

    // coalesced global write with bias
#pragma unroll 4
    for (int t = 0; t < 8; t++) {
        int fidx = tid + t * THREADS;
        int r = fidx >> 5, cs = fidx & 31;
        uint32_t u0, u1, u2, u3;
        LDS128(u0, u1, u2, u3, base + (uint32_t)((r * HPITCH + cs * 4) * 4));
        float4 bv = *(const float4*)&sbias[cs * 4];
        float4 o;
        o.x = __uint_as_float(u0) + bv.x;
        o.y = __uint_as_float(u1) + bv.y;
        o.z = __uint_as_float(u2) + bv.z;
        o.w = __uint_as_float(u3) + bv.w;
        *(float4*)&g_h[(size_t)(m0 + r) * NDIM + n0 + cs * 4] = o;
    }

    // column stats: 4 threads per column -> smem combine -> 1 partial/col/CTA
    {
        int col = tid & 127;
        int q = tid >> 7;
        float bcolv = sbias[col];
        float ss = 0.f, s2 = 0.f;
#pragma unroll 8
        for (int r = q * 32; r < q * 32 + 32; r++) {
            uint32_t u;
            LDS32(u, base + (uint32_t)((r * HPITCH + col) * 4));
            float v = __uint_as_float(u) + bcolv;
            ss += v;
            s2 = fmaf(v, v, s2);
        }
        STS32F(base + SRED_S + (q * 128 + col) * 4, ss);
        STS32F(base + SRED_Q + (q * 128 + col) * 4, s2);
    }
    __syncthreads();
    if (tid < 128) {
        float ss = 0.f, s2 = 0.f;
#pragma unroll
        for (int q = 0; q < 4; q++) {
            uint32_t u, v;
            LDS32(u, base + SRED_S + (q * 128 + tid) * 4);
            LDS32(v, base + SRED_Q + (q * 128 + tid) * 4);
            ss += __uint_as_float(u);
            s2 += __uint_as_float(v);
        }
        int slot = (n0 + tid) * NSLAB + blockIdx.y;
        g_ps[slot] = ss;
        g_pq[slot] = s2;
    }
}

// ---------------------------------------------------------------------------
// K3: finalize BN affine (one warp per column; coalesced partial reads)
// ---------------------------------------------------------------------------
__global__ void __launch_bounds__(256) finalize_kernel(const float* __restrict__ gamma,
                                                       const float* __restrict__ beta) {
    int col = blockIdx.x * 8 + (threadIdx.x >> 5);
    int lane = threadIdx.x & 31;
    double s = 0.0, q = 0.0;
    const float* ps = &g_ps[col * NSLAB];
    const float* pq = &g_pq[col * NSLAB];
    for (int i = lane; i < NSLAB; i += 32) {
        s += (double)ps[i];
        q += (double)pq[i];
    }
#pragma unroll
    for (int off = 16; off > 0; off >>= 1) {
        s += __shfl_down_sync(0xFFFFFFFFu, s, off);
        q += __shfl_down_sync(0xFFFFFFFFu, q, off);
    }
    if (lane == 0) {
        double mu = s / (double)MDIM;
        double var = q / (double)MDIM - mu * mu;
        double a = (double)gamma[col] / sqrt(var + 1e-5);
        g_a[col] = (float)a;
        g_c[col] = (float)((double)beta[col] - mu * a);
    }
}

// ---------------------------------------------------------------------------
// K4: heads — one warp handles 4 rows sharing the same node index
// (same weights/affine per lane across all 4 rows -> invariant loads amortized 4x)
// ---------------------------------------------------------------------------
__global__ void __launch_bounds__(256) heads_kernel(const float* __restrict__ Hbuf,
                                                    const float* __restrict__ Wa,
                                                    const float* __restrict__ ba,
                                                    const float* __restrict__ Wb,
                                                    const float* __restrict__ bb,
                                                    float* __restrict__ out) {
    const int gw = (int)((blockIdx.x * blockDim.x + threadIdx.x) >> 5);  // 0..32767
    const int lane = threadIdx.x & 31;
    const int node = gw & (NNODES - 1);
    const int bg = gw >> 11;                  // batch group 0..15 (4 rows each)
    const bool isA = (node < HALFN);

    const float4* ga4 = (const float4*)g_a;
    const float4* gc4 = (const float4*)g_c;
    const float4* wa4 = (const float4*)Wa;
    const float4* wb4 = (const float4*)Wb;

    float acc[4][5];
#pragma unroll
    for (int r = 0; r < 4; r++)
#pragma unroll
        for (int c = 0; c < 5; c++) acc[r][c] = 0.f;

#pragma unroll
    for (int i = 0; i < 4; i++) {
        int j4 = i * 32 + lane;               // group of 4 h-columns
        float4 av = ga4[j4];
        float4 cv = gc4[j4];
        float4 w0, w1, w2, w3, w4;
        if (isA) {
            w0 = wa4[j4 * 3 + 0];
            w1 = wa4[j4 * 3 + 1];
            w2 = wa4[j4 * 3 + 2];
        } else {
            w0 = wb4[j4 * 5 + 0];
            w1 = wb4[j4 * 5 + 1];
            w2 = wb4[j4 * 5 + 2];
            w3 = wb4[j4 * 5 + 3];
            w4 = wb4[j4 * 5 + 4];
        }
#pragma unroll
        for (int r = 0; r < 4; r++) {
            int row = (bg * 4 + r) * NNODES + node;
            float4 v = ((const float4*)(Hbuf + (size_t)row * NDIM))[j4];
            float t0 = fmaxf(fmaf(v.x, av.x, cv.x), 0.f);
            float t1 = fmaxf(fmaf(v.y, av.y, cv.y), 0.f);
            float t2 = fmaxf(fmaf(v.z, av.z, cv.z), 0.f);
            float t3 = fmaxf(fmaf(v.w, av.w, cv.w), 0.f);
            if (isA) {
                acc[r][0] = fmaf(t0, w0.x, acc[r][0]);
                acc[r][1] = fmaf(t0, w0.y, acc[r][1]);
                acc[r][2] = fmaf(t0, w0.z, acc[r][2]);
                acc[r][0] = fmaf(t1, w0.w, acc[r][0]);
                acc[r][1] = fmaf(t1, w1.x, acc[r][1]);
                acc[r][2] = fmaf(t1, w1.y, acc[r][2]);
                acc[r][0] = fmaf(t2, w1.z, acc[r][0]);
                acc[r][1] = fmaf(t2, w1.w, acc[r][1]);
                acc[r][2] = fmaf(t2, w2.x, acc[r][2]);
                acc[r][0] = fmaf(t3, w2.y, acc[r][0]);
                acc[r][1] = fmaf(t3, w2.z, acc[r][1]);
                acc[r][2] = fmaf(t3, w2.w, acc[r][2]);
            } else {
                acc[r][0] = fmaf(t0, w0.x, acc[r][0]);
                acc[r][1] = fmaf(t0, w0.y, acc[r][1]);
                acc[r][2] = fmaf(t0, w0.z, acc[r][2]);
                acc[r][3] = fmaf(t0, w0.w, acc[r][3]);
                acc[r][4] = fmaf(t0, w1.x, acc[r][4]);
                acc[r][0] = fmaf(t1, w1.y, acc[r][0]);
                acc[r][1] = fmaf(t1, w1.z, acc[r][1]);
                acc[r][2] = fmaf(t1, w1.w, acc[r][2]);
                acc[r][3] = fmaf(t1, w2.x, acc[r][3]);
                acc[r][4] = fmaf(t1, w2.y, acc[r][4]);
                acc[r][0] = fmaf(t2, w2.z, acc[r][0]);
                acc[r][1] = fmaf(t2, w2.w, acc[r][1]);
                acc[r][2] = fmaf(t2, w3.x, acc[r][2]);
                acc[r][3] = fmaf(t2, w3.y, acc[r][3]);
                acc[r][4] = fmaf(t2, w3.z, acc[r][4]);
                acc[r][0] = fmaf(t3, w3.w, acc[r][0]);
                acc[r][1] = fmaf(t3, w4.x, acc[r][1]);
                acc[r][2] = fmaf(t3, w4.y, acc[r][2]);
                acc[r][3] = fmaf(t3, w4.z, acc[r][3]);
                acc[r][4] = fmaf(t3, w4.w, acc[r][4]);
            }
        }
    }

    // warp reduction for all 20 accumulators
#pragma unroll
    for (int off = 16; off > 0; off >>= 1)
#pragma unroll
        for (int r = 0; r < 4; r++)
#pragma unroll
            for (int c = 0; c < 5; c++)
                acc[r][c] += __shfl_down_sync(0xFFFFFFFFu, acc[r][c], off);

    if (lane == 0) {
        const int C = isA ? 3 : 5;
        const float* bvec = isA ? ba : bb;
        float bv[5];
#pragma unroll
        for (int c = 0; c < 5; c++) bv[c] = (c < C) ? bvec[c] : 0.f;
#pragma unroll
        for (int r = 0; r < 4; r++) {
            int best = 0;
            float bestv = acc[r][0] + bv[0];
#pragma unroll
            for (int c = 1; c < 5; c++) {
                if (c < C) {
                    float lv = acc[r][c] + bv[c];
                    if (lv > bestv) { bestv = lv; best = c; }
                }
            }
            out[(bg * 4 + r) * NNODES + node] = (float)best;
        }
    }
}

// ---------------------------------------------------------------------------
// launch — minimal 4-kernel chain
// ---------------------------------------------------------------------------
extern "C" void kernel_launch(void* const* d_in, const int* in_sizes, int n_in,
                              void* d_out, int out_size) {
    const float* x     = (const float*)d_in[0];
    const float* W1    = (const float*)d_in[1];
    const float* b1    = (const float*)d_in[2];
    const float* gamma = (const float*)d_in[3];
    const float* beta  = (const float*)d_in[4];
    const float* Wa    = (const float*)d_in[5];
    const float* ba    = (const float*)d_in[6];
    const float* Wb    = (const float*)d_in[7];
    const float* bb    = (const float*)d_in[8];
    float* out = (float*)d_out;

    float* Hbuf;
    cudaGetSymbolAddress((void**)&Hbuf, g_h);

    cudaFuncSetAttribute(gemm_kernel, cudaFuncAttributeMaxDynamicSharedMemorySize,
                         SMEM_BYTES);

    splitB_kernel<<<64, 256>>>(W1);

    dim3 ggrid(NDIM / TILE_N, MDIM / TILE_M);   // (4, 1024)
    gemm_kernel<<<ggrid, THREADS, SMEM_BYTES>>>(x, b1);

    finalize_kernel<<<NDIM / 8, 256>>>(gamma, beta);

    // 32768 warps (2048 nodes x 16 batch-groups), 8 warps per block
    heads_kernel<<<4096, 256>>>(Hbuf, Wa, ba, Wb, bb, out);
}

// round 15
// speedup vs baseline: 1.0273x; 1.0273x over previous
#include <cuda_runtime.h>
#include <cuda_fp16.h>
#include <stdint.h>
#include <math.h>

// ---------------- problem constants ----------------
#define MDIM 131072   // B*N rows
#define KDIM 512      // D
#define NDIM 512      // H
#define NNODES 2048
#define HALFN 1024

#define TILE_M 128
#define TILE_N 128
#define KC 32
#define NCHUNK 16
#define THREADS 512
#define NSLAB 1024
#define PITCH 80      // bytes per row in fp16 limb tiles (64 data + 16 pad)

// smem (bytes from 128-aligned dyn base), 3 stages:
//   A limbs: (s*2+p)*10240     -> 0..61440
//   B limbs: 61440 + (s*2+p)*10240 -> ..122880
//   stat red: 122880 (2 x 2KB)
#define A_OFF(s, p) ((((s) * 2) + (p)) * 10240)
#define B_OFF(s, p) (61440 + (((s) * 2) + (p)) * 10240)
#define SRED_S      122880
#define SRED_Q      124928
#define SMEM_BYTES  (126976 + 128)
#define HPITCH 132            // floats; epilogue staging (reuses tile region)
#define SCALE_UP 4096.0f
#define SCALE_DN (1.0f / 4096.0f)

// ---------------- device scratch ----------------
__device__ float  g_h[(size_t)MDIM * NDIM];        // 256 MB hidden
__device__ float  g_ps[NDIM * NSLAB];              // column-major partials [col][slab]
__device__ float  g_pq[NDIM * NSLAB];
__device__ float  g_a[NDIM];
__device__ float  g_c[NDIM];
__device__ __align__(16) __half g_Bh[KDIM * NDIM]; // W1^T limbs, [n][k]
__device__ __align__(16) __half g_Bm[KDIM * NDIM]; // scaled by 4096

// ---------------- PTX helpers ----------------
__device__ __forceinline__ uint32_t smem_u32(const void* p) {
    uint32_t a;
    asm("{ .reg .u64 t; cvta.to.shared.u64 t, %1; cvt.u32.u64 %0, t; }" : "=r"(a) : "l"(p));
    return a;
}
#define LDS128(r0, r1, r2, r3, addr) \
    asm volatile("ld.shared.v4.b32 {%0, %1, %2, %3}, [%4];" \
                 : "=r"(r0), "=r"(r1), "=r"(r2), "=r"(r3) : "r"(addr))
#define LDS32(r0, addr) \
    asm volatile("ld.shared.b32 %0, [%1];" : "=r"(r0) : "r"(addr))
#define STS128(r0, r1, r2, r3, addr) \
    asm volatile("st.shared.v4.b32 [%0], {%1, %2, %3, %4};" \
                 :: "r"(addr), "r"(r0), "r"(r1), "r"(r2), "r"(r3) : "memory")
#define STS64F(addr, x, y) \
    asm volatile("st.shared.v2.f32 [%0], {%1, %2};" :: "r"(addr), "f"(x), "f"(y) : "memory")
#define STS32F(addr, x) \
    asm volatile("st.shared.f32 [%0], %1;" :: "r"(addr), "f"(x) : "memory")

__device__ __forceinline__ void ldsm_x4(uint32_t* r, uint32_t addr) {
    asm volatile("ldmatrix.sync.aligned.m8n8.x4.shared.b16 {%0,%1,%2,%3}, [%4];"
                 : "=r"(r[0]), "=r"(r[1]), "=r"(r[2]), "=r"(r[3]) : "r"(addr));
}
__device__ __forceinline__ void mma16816(float* d, const uint32_t* a, const uint32_t* b) {
    asm volatile(
        "mma.sync.aligned.m16n8k16.row.col.f32.f16.f16.f32 "
        "{%0,%1,%2,%3}, {%4,%5,%6,%7}, {%8,%9}, {%0,%1,%2,%3};"
        : "+f"(d[0]), "+f"(d[1]), "+f"(d[2]), "+f"(d[3])
        : "r"(a[0]), "r"(a[1]), "r"(a[2]), "r"(a[3]), "r"(b[0]), "r"(b[1]));
}
__device__ __forceinline__ void cpasync16(uint32_t dst, const void* src) {
    asm volatile("cp.async.cg.shared.global [%0], [%1], 16;" :: "r"(dst), "l"(src));
}
#define CP_COMMIT() asm volatile("cp.async.commit_group;" ::: "memory")
#define CP_WAIT1()  asm volatile("cp.async.wait_group 1;" ::: "memory")
#define CP_WAIT0()  asm volatile("cp.async.wait_group 0;" ::: "memory")

// scalar split (splitB only)
__device__ __forceinline__ void split2(float v, uint32_t& h, uint32_t& m) {
    __half hh = __float2half_rn(v);
    float r = (v - __half2float(hh)) * SCALE_UP;
    __half hm = __float2half_rn(r);
    h = (uint32_t)__half_as_ushort(hh);
    m = (uint32_t)__half_as_ushort(hm);
}

// packed split of a float pair
__device__ __forceinline__ void split2x2(float x0, float x1, uint32_t& hp, uint32_t& mp) {
    __half2 hh = __floats2half2_rn(x0, x1);
    float2 hf = __half22float2(hh);
    __half2 mm = __floats2half2_rn((x0 - hf.x) * SCALE_UP, (x1 - hf.y) * SCALE_UP);
    hp = *(uint32_t*)&hh;
    mp = *(uint32_t*)&mm;
}

// ---------------------------------------------------------------------------
// K1: split W1 [k][n] fp32 -> 2 fp16 matrices [n][k]; smem-tiled transpose
// ---------------------------------------------------------------------------
__global__ void __launch_bounds__(256) splitB_kernel(const float* __restrict__ W1) {
    __shared__ unsigned short sh[64][80];
    __shared__ unsigned short sm[64][80];
    const int n0 = (blockIdx.x & 7) * 64;
    const int k0 = (blockIdx.x >> 3) * 64;
    const int tid = threadIdx.x;

#pragma unroll
    for (int t = 0; t < 16; t++) {
        int idx = t * 256 + tid;
        int kk = idx >> 6, nn = idx & 63;
        float v = W1[(size_t)(k0 + kk) * NDIM + n0 + nn];
        uint32_t h, m;
        split2(v, h, m);
        sh[nn][kk] = (unsigned short)h;
        sm[nn][kk] = (unsigned short)m;
    }
    __syncthreads();

#pragma unroll
    for (int t = 0; t < 2; t++) {
        int idx = t * 256 + tid;
        int nn = idx >> 3, seg = idx & 7;
        uint4 vh = *(const uint4*)&sh[nn][seg * 8];
        uint4 vm = *(const uint4*)&sm[nn][seg * 8];
        *(uint4*)&g_Bh[(size_t)(n0 + nn) * KDIM + k0 + seg * 8] = vh;
        *(uint4*)&g_Bm[(size_t)(n0 + nn) * KDIM + k0 + seg * 8] = vm;
    }
}

// ---------------------------------------------------------------------------
// K2: fp16x2 HMMA GEMM  h = x @ W1 + b1, fused per-CTA column stats
// 512 threads, warp tile 32x32, 3-stage pipeline, convert mid-MMA  (champion)
// ---------------------------------------------------------------------------
__device__ __forceinline__ void issue_B(uint32_t base, int n0, int c, int tid) {
    const int s = c % 3;
    int p = tid >> 8;
    int r = (tid >> 1) & 127;
    int sg = (tid & 1) * 32;
    const __half* gb = (p == 0) ? g_Bh : g_Bm;
    const __half* src = gb + (size_t)(n0 + r) * KDIM + c * KC + (sg >> 1);
    uint32_t dst = base + B_OFF(s, p) + r * PITCH + sg;
    cpasync16(dst, src);
    cpasync16(dst + 16, src + 8);
    CP_COMMIT();
}

__device__ __forceinline__ void ldg_x(const float* __restrict__ X, int m0, int c,
                                      int xrow, int xf, float4& xa, float4& xb) {
    const float4* src = (const float4*)(X + (size_t)(m0 + xrow) * KDIM + c * KC + xf);
    xa = src[0];
    xb = src[1];
}

__device__ __forceinline__ void convert_sts(uint32_t base, int c, int xrow, int xf,
                                            const float4& xa, const float4& xb) {
    const int s = c % 3;
    uint32_t h0, h1, h2, h3, m0v, m1, m2, m3;
    split2x2(xa.x, xa.y, h0, m0v);
    split2x2(xa.z, xa.w, h1, m1);
    split2x2(xb.x, xb.y, h2, m2);
    split2x2(xb.z, xb.w, h3, m3);
    uint32_t ro = (uint32_t)(xrow * PITCH + xf * 2);
    STS128(h0, h1, h2, h3, base + A_OFF(s, 0) + ro);
    STS128(m0v, m1, m2, m3, base + A_OFF(s, 1) + ro);
}

__global__ void __launch_bounds__(THREADS, 1)
gemm_kernel(const float* __restrict__ X, const float* __restrict__ b1) {
    extern __shared__ char dyn[];
    __shared__ float sbias[TILE_N];

    const uint32_t base = (smem_u32(dyn) + 127u) & ~127u;
    const int tid = threadIdx.x;
    const int wid = tid >> 5;
    const int lane = tid & 31;
    const int m0 = blockIdx.y * TILE_M;
    const int n0 = blockIdx.x * TILE_N;

    if (tid < TILE_N) sbias[tid] = b1[n0 + tid];

    const int wm = (wid & 3) * 32;
    const int wn = (wid >> 2) * 32;
    const int xrow = tid >> 2;
    const int xf = (tid & 3) * 8;

    float a1[2][4][4], a2[2][4][4];
#pragma unroll
    for (int i = 0; i < 2; i++)
#pragma unroll
        for (int j = 0; j < 4; j++)
#pragma unroll
            for (int q = 0; q < 4; q++) { a1[i][j][q] = 0.f; a2[i][j][q] = 0.f; }

    // prologue: chunks 0 and 1
    {
        float4 xa, xb;
        issue_B(base, n0, 0, tid);
        issue_B(base, n0, 1, tid);
        ldg_x(X, m0, 0, xrow, xf, xa, xb);
        convert_sts(base, 0, xrow, xf, xa, xb);
        ldg_x(X, m0, 1, xrow, xf, xa, xb);
        convert_sts(base, 1, xrow, xf, xa, xb);
        CP_WAIT1();   // B(0) complete
        __syncthreads();
    }

    // lane-constant ldsm address components
    const int arow = lane & 15;
    const int acolh = (lane >> 4) * 16;
    const int bm = lane >> 3;
    const int brow = ((bm & 2) << 2) + (lane & 7);
    const int bko = (bm & 1) * 16;

    for (int c = 0; c < NCHUNK; c++) {
        const int s = c % 3;
        float4 xa, xb;
        const bool pre = (c + 2 < NCHUNK);
        if (pre) {
            ldg_x(X, m0, c + 2, xrow, xf, xa, xb);   // consumed mid-MMA below
            issue_B(base, n0, c + 2, tid);
        }

#pragma unroll
        for (int k16 = 0; k16 < 2; k16++) {
            const uint32_t koA = (uint32_t)(k16 * 32 + acolh);
            const uint32_t koB = (uint32_t)(k16 * 32 + bko);
            uint32_t aH[2][4], aM[2][4];
#pragma unroll
            for (int i = 0; i < 2; i++) {
                uint32_t ra = (uint32_t)((wm + i * 16 + arow) * PITCH);
                ldsm_x4(aH[i], base + A_OFF(s, 0) + ra + koA);
                ldsm_x4(aM[i], base + A_OFF(s, 1) + ra + koA);
            }
#pragma unroll
            for (int jj = 0; jj < 2; jj++) {
                uint32_t rb = (uint32_t)((wn + jj * 16 + brow) * PITCH) + koB;
                uint32_t bh[4], bmr[4];
                ldsm_x4(bh, base + B_OFF(s, 0) + rb);
                ldsm_x4(bmr, base + B_OFF(s, 1) + rb);
#pragma unroll
                for (int i = 0; i < 2; i++) {
                    mma16816(a1[i][jj * 2 + 0], aH[i], bh + 0);
                    mma16816(a1[i][jj * 2 + 1], aH[i], bh + 2);
                    mma16816(a2[i][jj * 2 + 0], aM[i], bh + 0);
                    mma16816(a2[i][jj * 2 + 1], aM[i], bh + 2);
                    mma16816(a2[i][jj * 2 + 0], aH[i], bmr + 0);
                    mma16816(a2[i][jj * 2 + 1], aH[i], bmr + 2);
                }
            }
            // convert sandwiched between the two k16 MMA batches
            if (k16 == 0 && pre) convert_sts(base, c + 2, xrow, xf, xa, xb);
        }

        if (pre) {
            CP_WAIT1();          // B(c+1) complete
        } else if (c + 1 < NCHUNK) {
            CP_WAIT0();
        }
        if (c + 1 < NCHUNK) __syncthreads();
    }

    // ---------------- epilogue: combine limbs, stage to smem ----------------
    __syncthreads();
#pragma unroll
    for (int i = 0; i < 2; i++)
#pragma unroll
        for (int j = 0; j < 4; j++) {
            int r0 = wm + i * 16 + (lane >> 2);
            int c0 = wn + j * 8 + (lane & 3) * 2;
            float v0 = a1[i][j][0] + a2[i][j][0] * SCALE_DN;
            float v1 = a1[i][j][1] + a2[i][j][1] * SCALE_DN;
            float v2 = a1[i][j][2] + a2[i][j][2] * SCALE_DN;
            float v3 = a1[i][j][3] + a2[i][j][3] * SCALE_DN;
            STS64F(base + (uint32_t)((r0 * HPITCH + c0) * 4), v0, v1);
            STS64F(base + (uint32_t)(((r0 + 8) * HPITCH + c0) * 4), v2, v3);
        }
    __syncthreads();

    // coalesced global write with bias
#pragma unroll 4
    for (int t = 0; t < 8; t++) {
        int fidx = tid + t * THREADS;
        int r = fidx >> 5, cs = fidx & 31;
        uint32_t u0, u1, u2, u3;
        LDS128(u0, u1, u2, u3, base + (uint32_t)((r * HPITCH + cs * 4) * 4));
        float4 bv = *(const float4*)&sbias[cs * 4];
        float4 o;
        o.x = __uint_as_float(u0) + bv.x;
        o.y = __uint_as_float(u1) + bv.y;
        o.z = __uint_as_float(u2) + bv.z;
        o.w = __uint_as_float(u3) + bv.w;
        *(float4*)&g_h[(size_t)(m0 + r) * NDIM + n0 + cs * 4] = o;
    }

    // column stats: 4 threads per column -> smem combine -> 1 partial/col/CTA
    {
        int col = tid & 127;
        int q = tid >> 7;
        float bcolv = sbias[col];
        float ss = 0.f, s2 = 0.f;
#pragma unroll 8
        for (int r = q * 32; r < q * 32 + 32; r++) {
            uint32_t u;
            LDS32(u, base + (uint32_t)((r * HPITCH + col) * 4));
            float v = __uint_as_float(u) + bcolv;
            ss += v;
            s2 = fmaf(v, v, s2);
        }
        STS32F(base + SRED_S + (q * 128 + col) * 4, ss);
        STS32F(base + SRED_Q + (q * 128 + col) * 4, s2);
    }
    __syncthreads();
    if (tid < 128) {
        float ss = 0.f, s2 = 0.f;
#pragma unroll
        for (int q = 0; q < 4; q++) {
            uint32_t u, v;
            LDS32(u, base + SRED_S + (q * 128 + tid) * 4);
            LDS32(v, base + SRED_Q + (q * 128 + tid) * 4);
            ss += __uint_as_float(u);
            s2 += __uint_as_float(v);
        }
        int slot = (n0 + tid) * NSLAB + blockIdx.y;
        g_ps[slot] = ss;
        g_pq[slot] = s2;
    }
}

// ---------------------------------------------------------------------------
// K3: finalize BN affine (one warp per column; coalesced partial reads)
// ---------------------------------------------------------------------------
__global__ void __launch_bounds__(256) finalize_kernel(const float* __restrict__ gamma,
                                                       const float* __restrict__ beta) {
    int col = blockIdx.x * 8 + (threadIdx.x >> 5);
    int lane = threadIdx.x & 31;
    double s = 0.0, q = 0.0;
    const float* ps = &g_ps[col * NSLAB];
    const float* pq = &g_pq[col * NSLAB];
    for (int i = lane; i < NSLAB; i += 32) {
        s += (double)ps[i];
        q += (double)pq[i];
    }
#pragma unroll
    for (int off = 16; off > 0; off >>= 1) {
        s += __shfl_down_sync(0xFFFFFFFFu, s, off);
        q += __shfl_down_sync(0xFFFFFFFFu, q, off);
    }
    if (lane == 0) {
        double mu = s / (double)MDIM;
        double var = q / (double)MDIM - mu * mu;
        double a = (double)gamma[col] / sqrt(var + 1e-5);
        g_a[col] = (float)a;
        g_c[col] = (float)((double)beta[col] - mu * a);
    }
}

// ---------------------------------------------------------------------------
// K4: heads — one warp handles 2 rows sharing the same node index
// (invariant weight/affine loads amortized 2x; modest registers -> high occ)
// ---------------------------------------------------------------------------
__global__ void __launch_bounds__(256) heads_kernel(const float* __restrict__ Hbuf,
                                                    const float* __restrict__ Wa,
                                                    const float* __restrict__ ba,
                                                    const float* __restrict__ Wb,
                                                    const float* __restrict__ bb,
                                                    float* __restrict__ out) {
    const int gw = (int)((blockIdx.x * blockDim.x + threadIdx.x) >> 5);  // 0..65535
    const int lane = threadIdx.x & 31;
    const int node = gw & (NNODES - 1);
    const int bg = gw >> 11;                  // batch group 0..31 (2 rows each)
    const bool isA = (node < HALFN);

    const float4* ga4 = (const float4*)g_a;
    const float4* gc4 = (const float4*)g_c;
    const float4* wa4 = (const float4*)Wa;
    const float4* wb4 = (const float4*)Wb;

    float acc[2][5];
#pragma unroll
    for (int r = 0; r < 2; r++)
#pragma unroll
        for (int c = 0; c < 5; c++) acc[r][c] = 0.f;

#pragma unroll
    for (int i = 0; i < 4; i++) {
        int j4 = i * 32 + lane;               // group of 4 h-columns
        float4 av = ga4[j4];
        float4 cv = gc4[j4];
        float4 w0, w1, w2, w3, w4;
        if (isA) {
            w0 = wa4[j4 * 3 + 0];
            w1 = wa4[j4 * 3 + 1];
            w2 = wa4[j4 * 3 + 2];
        } else {
            w0 = wb4[j4 * 5 + 0];
            w1 = wb4[j4 * 5 + 1];
            w2 = wb4[j4 * 5 + 2];
            w3 = wb4[j4 * 5 + 3];
            w4 = wb4[j4 * 5 + 4];
        }
#pragma unroll
        for (int r = 0; r < 2; r++) {
            int row = (bg * 2 + r) * NNODES + node;
            float4 v = __ldcs((const float4*)(Hbuf + (size_t)row * NDIM) + j4);
            float t0 = fmaxf(fmaf(v.x, av.x, cv.x), 0.f);
            float t1 = fmaxf(fmaf(v.y, av.y, cv.y), 0.f);
            float t2 = fmaxf(fmaf(v.z, av.z, cv.z), 0.f);
            float t3 = fmaxf(fmaf(v.w, av.w, cv.w), 0.f);
            if (isA) {
                acc[r][0] = fmaf(t0, w0.x, acc[r][0]);
                acc[r][1] = fmaf(t0, w0.y, acc[r][1]);
                acc[r][2] = fmaf(t0, w0.z, acc[r][2]);
                acc[r][0] = fmaf(t1, w0.w, acc[r][0]);
                acc[r][1] = fmaf(t1, w1.x, acc[r][1]);
                acc[r][2] = fmaf(t1, w1.y, acc[r][2]);
                acc[r][0] = fmaf(t2, w1.z, acc[r][0]);
                acc[r][1] = fmaf(t2, w1.w, acc[r][1]);
                acc[r][2] = fmaf(t2, w2.x, acc[r][2]);
                acc[r][0] = fmaf(t3, w2.y, acc[r][0]);
                acc[r][1] = fmaf(t3, w2.z, acc[r][1]);
                acc[r][2] = fmaf(t3, w2.w, acc[r][2]);
            } else {
                acc[r][0] = fmaf(t0, w0.x, acc[r][0]);
                acc[r][1] = fmaf(t0, w0.y, acc[r][1]);
                acc[r][2] = fmaf(t0, w0.z, acc[r][2]);
                acc[r][3] = fmaf(t0, w0.w, acc[r][3]);
                acc[r][4] = fmaf(t0, w1.x, acc[r][4]);
                acc[r][0] = fmaf(t1, w1.y, acc[r][0]);
                acc[r][1] = fmaf(t1, w1.z, acc[r][1]);
                acc[r][2] = fmaf(t1, w1.w, acc[r][2]);
                acc[r][3] = fmaf(t1, w2.x, acc[r][3]);
                acc[r][4] = fmaf(t1, w2.y, acc[r][4]);
                acc[r][0] = fmaf(t2, w2.z, acc[r][0]);
                acc[r][1] = fmaf(t2, w2.w, acc[r][1]);
                acc[r][2] = fmaf(t2, w3.x, acc[r][2]);
                acc[r][3] = fmaf(t2, w3.y, acc[r][3]);
                acc[r][4] = fmaf(t2, w3.z, acc[r][4]);
                acc[r][0] = fmaf(t3, w3.w, acc[r][0]);
                acc[r][1] = fmaf(t3, w4.x, acc[r][1]);
                acc[r][2] = fmaf(t3, w4.y, acc[r][2]);
                acc[r][3] = fmaf(t3, w4.z, acc[r][3]);
                acc[r][4] = fmaf(t3, w4.w, acc[r][4]);
            }
        }
    }

    // warp reduction for the 10 accumulators
#pragma unroll
    for (int off = 16; off > 0; off >>= 1)
#pragma unroll
        for (int r = 0; r < 2; r++)
#pragma unroll
            for (int c = 0; c < 5; c++)
                acc[r][c] += __shfl_down_sync(0xFFFFFFFFu, acc[r][c], off);

    if (lane == 0) {
        const int C = isA ? 3 : 5;
        const float* bvec = isA ? ba : bb;
        float bv[5];
#pragma unroll
        for (int c = 0; c < 5; c++) bv[c] = (c < C) ? bvec[c] : 0.f;
#pragma unroll
        for (int r = 0; r < 2; r++) {
            int best = 0;
            float bestv = acc[r][0] + bv[0];
#pragma unroll
            for (int c = 1; c < 5; c++) {
                if (c < C) {
                    float lv = acc[r][c] + bv[c];
                    if (lv > bestv) { bestv = lv; best = c; }
                }
            }
            out[(bg * 2 + r) * NNODES + node] = (float)best;
        }
    }
}

// ---------------------------------------------------------------------------
// launch — minimal 4-kernel chain
// ---------------------------------------------------------------------------
extern "C" void kernel_launch(void* const* d_in, const int* in_sizes, int n_in,
                              void* d_out, int out_size) {
    const float* x     = (const float*)d_in[0];
    const float* W1    = (const float*)d_in[1];
    const float* b1    = (const float*)d_in[2];
    const float* gamma = (const float*)d_in[3];
    const float* beta  = (const float*)d_in[4];
    const float* Wa    = (const float*)d_in[5];
    const float* ba    = (const float*)d_in[6];
    const float* Wb    = (const float*)d_in[7];
    const float* bb    = (const float*)d_in[8];
    float* out = (float*)d_out;

    float* Hbuf;
    cudaGetSymbolAddress((void**)&Hbuf, g_h);

    cudaFuncSetAttribute(gemm_kernel, cudaFuncAttributeMaxDynamicSharedMemorySize,
                         SMEM_BYTES);

    splitB_kernel<<<64, 256>>>(W1);

    dim3 ggrid(NDIM / TILE_N, MDIM / TILE_M);   // (4, 1024)
    gemm_kernel<<<ggrid, THREADS, SMEM_BYTES>>>(x, b1);

    finalize_kernel<<<NDIM / 8, 256>>>(gamma, beta);

    // 65536 warps (2048 nodes x 32 batch-groups), 8 warps per block
    heads_kernel<<<8192, 256>>>(Hbuf, Wa, ba, Wb, bb, out);
}